// round 6
// baseline (speedup 1.0000x reference)
#include <cuda_runtime.h>
#include <cstdint>

#define BDIM 4096
#define DDIM 1024
#define KSEL 1024
#define MARGIN 0.5f
#define EPSV 1e-6f
#define BIGV 1e6f
#define CEPS (1024.0f * 1e-6f * 1e-6f)   /* D * eps^2 */
#define SCALE (1.0f / (4096.0f * 1024.0f))
#define NBINS 4096

// GEMM tiling: block 128x128, BK=32, 128 threads (4 warps of 64x64)
#define GM 128
#define GN 128
#define BK 32
#define NKT (DDIM / BK)              /* 32 */
#define RSB 160                      /* smem row stride bytes (32 fl + pad) */
#define OFF_B (128 * RSB)            /* 20480 */
#define STAGE_B (2 * 128 * RSB)      /* 40960 */
#define SM_BUF0 1024
#define GSMEM (SM_BUF0 + 2 * STAGE_B)
#define STAGE_TX 32768u              /* 256 rows x 128B actual payload */
#define CSTR 132                     /* epilogue transpose-stage stride (floats) */

// ---------------- device scratch (static: no allocations allowed) ----------
__device__ float g_dist[(size_t)BDIM * BDIM];
__device__ float g_distT[(size_t)BDIM * BDIM];
__device__ float g_a[BDIM];   // ||x||^2 + 2*eps*sum(x)
__device__ float g_b[BDIM];   // ||y||^2 - 2*eps*sum(y)

// ---------------- helpers --------------------------------------------------
__device__ __forceinline__ uint32_t smem_u32(const void* p) {
    return (uint32_t)__cvta_generic_to_shared(p);
}
__device__ __forceinline__ void mbar_init(uint32_t m, uint32_t cnt) {
    asm volatile("mbarrier.init.shared.b64 [%0], %1;" :: "r"(m), "r"(cnt) : "memory");
}
__device__ __forceinline__ void mbar_expect(uint32_t m, uint32_t bytes) {
    asm volatile("mbarrier.arrive.expect_tx.shared.b64 _, [%0], %1;"
                 :: "r"(m), "r"(bytes) : "memory");
}
__device__ __forceinline__ void mbar_wait(uint32_t m, uint32_t ph) {
    asm volatile(
        "{\n\t.reg .pred P;\n"
        "W%=:\n\t"
        "mbarrier.try_wait.parity.acquire.cta.shared::cta.b64 P, [%0], %1, 0x989680;\n\t"
        "@P bra D%=;\n\t"
        "bra W%=;\n"
        "D%=:\n\t}"
        :: "r"(m), "r"(ph) : "memory");
}
__device__ __forceinline__ void bulk_cp(uint32_t dst, const void* src,
                                        uint32_t bytes, uint32_t mbar) {
    asm volatile(
        "cp.async.bulk.shared::cluster.global.mbarrier::complete_tx::bytes "
        "[%0], [%1], %2, [%3];"
        :: "r"(dst), "l"(src), "r"(bytes), "r"(mbar) : "memory");
}
__device__ __forceinline__ void mma_tf32(float* c, uint32_t a0, uint32_t a1,
                                         uint32_t a2, uint32_t a3,
                                         uint32_t b0, uint32_t b1) {
    asm volatile(
        "mma.sync.aligned.m16n8k8.row.col.f32.tf32.tf32.f32 "
        "{%0,%1,%2,%3}, {%4,%5,%6,%7}, {%8,%9}, {%0,%1,%2,%3};"
        : "+f"(c[0]), "+f"(c[1]), "+f"(c[2]), "+f"(c[3])
        : "r"(a0), "r"(a1), "r"(a2), "r"(a3), "r"(b0), "r"(b1));
}

// ---------------- small kernels -------------------------------------------
__global__ void zero_out_kernel(float* out) {
    if (threadIdx.x == 0) { out[0] = 0.f; out[1] = 0.f; }
}

__global__ void rowstats_kernel(const float* __restrict__ X,
                                const float* __restrict__ Y) {
    __shared__ float r1s[8], r2s[8];
    int r = blockIdx.x;
    const float* p = (blockIdx.y == 0) ? X : Y;
    p += (size_t)r * DDIM;
    float s1 = 0.f, s2 = 0.f;
    for (int i = threadIdx.x; i < DDIM; i += 256) {
        float v = p[i]; s1 += v; s2 += v * v;
    }
    for (int o = 16; o; o >>= 1) {
        s1 += __shfl_down_sync(0xffffffffu, s1, o);
        s2 += __shfl_down_sync(0xffffffffu, s2, o);
    }
    int lane = threadIdx.x & 31, w = threadIdx.x >> 5;
    if (lane == 0) { r1s[w] = s1; r2s[w] = s2; }
    __syncthreads();
    if (threadIdx.x == 0) {
        s1 = 0.f; s2 = 0.f;
        for (int i = 0; i < 8; i++) { s1 += r1s[i]; s2 += r2s[i]; }
        if (blockIdx.y == 0) g_a[r] = s2 + 2.f * EPSV * s1;
        else                 g_b[r] = s2 - 2.f * EPSV * s1;
    }
}

// ---------------- tf32 mma.sync GEMM + fused transpose --------------------
// Loads via cp.async.bulk (TMA 1D): one 128B DMA per tile row, completion
// via mbarrier expect_tx. Kills the LDGSTS issue bottleneck of round 5.
__global__ __launch_bounds__(128, 2)
void gemm_dist_kernel(const float* __restrict__ X, const float* __restrict__ Y) {
    extern __shared__ char smem[];
    const uint32_t sb = smem_u32(smem);
    const int tid  = threadIdx.x;
    const int lane = tid & 31, wid = tid >> 5;
    const int wm = wid & 1, wn = wid >> 1;   // 2x2 warp grid, 64x64 each
    const int g  = lane >> 2, tg = lane & 3;
    const int m0 = blockIdx.y * GM, n0 = blockIdx.x * GN;

    const uint32_t mb0 = sb, mb1 = sb + 16;

    if (tid == 0) { mbar_init(mb0, 1); mbar_init(mb1, 1); }
    __syncthreads();

    float acc[4][8][4];
#pragma unroll
    for (int mt = 0; mt < 4; mt++)
#pragma unroll
        for (int nt = 0; nt < 8; nt++)
#pragma unroll
            for (int q = 0; q < 4; q++) acc[mt][nt][q] = 0.f;

    const float* xb = X + (size_t)m0 * DDIM;
    const float* yb = Y + (size_t)n0 * DDIM;

    // stage loader: thread t DMAs A row t and B row t (128B each)
#define LOAD_STAGE(KT)                                                        \
    {                                                                         \
        int _b = (KT) & 1;                                                    \
        uint32_t _mb = _b ? mb1 : mb0;                                        \
        uint32_t _buf = sb + SM_BUF0 + (uint32_t)_b * STAGE_B;                \
        int _c0 = (KT) * BK;                                                  \
        if (tid == 0) mbar_expect(_mb, STAGE_TX);                             \
        bulk_cp(_buf + tid * RSB, xb + (size_t)tid * DDIM + _c0, 128, _mb);   \
        bulk_cp(_buf + OFF_B + tid * RSB, yb + (size_t)tid * DDIM + _c0,      \
                128, _mb);                                                    \
    }

    LOAD_STAGE(0);
    LOAD_STAGE(1);

    for (int kt = 0; kt < NKT; kt++) {
        mbar_wait((kt & 1) ? mb1 : mb0, (kt >> 1) & 1);

        const char* abuf = smem + SM_BUF0 + (size_t)(kt & 1) * STAGE_B;
        const char* bbuf = abuf + OFF_B;

#pragma unroll
        for (int s = 0; s < 4; s++) {
            uint32_t A0[4], A1[4], A2[4], A3[4];
#pragma unroll
            for (int mt = 0; mt < 4; mt++) {
                int r = wm * 64 + mt * 16 + g;
                float2 lo = *(const float2*)(abuf + r * RSB + s * 32 + tg * 8);
                float2 hi = *(const float2*)(abuf + (r + 8) * RSB + s * 32 + tg * 8);
                A0[mt] = __float_as_uint(lo.x);
                A2[mt] = __float_as_uint(lo.y);
                A1[mt] = __float_as_uint(hi.x);
                A3[mt] = __float_as_uint(hi.y);
            }
#pragma unroll
            for (int nt = 0; nt < 8; nt++) {
                int n = wn * 64 + nt * 8 + g;
                float2 bv = *(const float2*)(bbuf + n * RSB + s * 32 + tg * 8);
                uint32_t B0 = __float_as_uint(bv.x);
                uint32_t B1 = __float_as_uint(bv.y);
                mma_tf32(acc[0][nt], A0[0], A1[0], A2[0], A3[0], B0, B1);
                mma_tf32(acc[1][nt], A0[1], A1[1], A2[1], A3[1], B0, B1);
                mma_tf32(acc[2][nt], A0[2], A1[2], A2[2], A3[2], B0, B1);
                mma_tf32(acc[3][nt], A0[3], A1[3], A2[3], A3[3], B0, B1);
            }
        }
        __syncthreads();                 // all warps done reading this buffer
        if (kt + 2 < NKT) LOAD_STAGE(kt + 2);
    }

    // epilogue: distances; direct write to g_dist, smem-staged for g_distT
    float* Csh = (float*)smem;
#pragma unroll
    for (int mt = 0; mt < 4; mt++) {
        int r0 = wm * 64 + mt * 16 + g;
        float a0 = g_a[m0 + r0] + CEPS;
        float a1 = g_a[m0 + r0 + 8] + CEPS;
#pragma unroll
        for (int nt = 0; nt < 8; nt++) {
            int c = wn * 64 + nt * 8 + 2 * tg;
            float b0 = g_b[n0 + c], b1 = g_b[n0 + c + 1];
            float* a4 = acc[mt][nt];
            float o00 = sqrtf(fmaxf(a0 + b0 - 2.f * a4[0], 0.f));
            float o01 = sqrtf(fmaxf(a0 + b1 - 2.f * a4[1], 0.f));
            float o10 = sqrtf(fmaxf(a1 + b0 - 2.f * a4[2], 0.f));
            float o11 = sqrtf(fmaxf(a1 + b1 - 2.f * a4[3], 0.f));
            *(float2*)&g_dist[(size_t)(m0 + r0) * BDIM + n0 + c] =
                make_float2(o00, o01);
            *(float2*)&g_dist[(size_t)(m0 + r0 + 8) * BDIM + n0 + c] =
                make_float2(o10, o11);
            Csh[c * CSTR + r0]           = o00;
            Csh[(c + 1) * CSTR + r0]     = o01;
            Csh[c * CSTR + r0 + 8]       = o10;
            Csh[(c + 1) * CSTR + r0 + 8] = o11;
        }
    }
    __syncthreads();
    // write transposed tile: 128 rows x 32 float4
#pragma unroll
    for (int i = tid; i < 128 * 32; i += 128) {
        int j = i >> 5, q = i & 31;
        float4 v = *(float4*)&Csh[j * CSTR + 4 * q];
        *(float4*)&g_distT[(size_t)(n0 + j) * BDIM + m0 + 4 * q] = v;
    }
}

// ---------------- block helpers (512 threads) -----------------------------
__device__ __forceinline__ void block_reduce_if(int& ci, float& sf, int tid,
                                                int* ired, float* fred) {
    for (int o = 16; o; o >>= 1) {
        ci += __shfl_down_sync(0xffffffffu, ci, o);
        sf += __shfl_down_sync(0xffffffffu, sf, o);
    }
    int lane = tid & 31, w = tid >> 5;
    if (lane == 0) { ired[w] = ci; fred[w] = sf; }
    __syncthreads();
    if (tid < 32) {
        int c = (tid < 16) ? ired[tid] : 0;
        float s = (tid < 16) ? fred[tid] : 0.f;
        for (int o = 8; o; o >>= 1) {
            c += __shfl_down_sync(0xffffffffu, c, o);
            s += __shfl_down_sync(0xffffffffu, s, o);
        }
        if (tid == 0) { ired[16] = c; fred[16] = s; }
    }
    __syncthreads();
    ci = ired[16]; sf = fred[16];
    __syncthreads();
}

__device__ __forceinline__ int block_exscan512(int v, int tid, int* sc) {
    int lane = tid & 31, w = tid >> 5;
    int x = v;
    for (int o = 1; o < 32; o <<= 1) {
        int t = __shfl_up_sync(0xffffffffu, x, o);
        if (lane >= o) x += t;
    }
    if (lane == 31) sc[w] = x;
    __syncthreads();
    if (tid < 32) {
        int ws = (tid < 16) ? sc[tid] : 0;
        for (int o = 1; o < 16; o <<= 1) {
            int t = __shfl_up_sync(0xffffffffu, ws, o);
            if (lane >= o) ws += t;
        }
        if (tid < 16) sc[tid] = ws;
    }
    __syncthreads();
    int off = (w > 0) ? sc[w - 1] : 0;
    int r = off + x - v;
    __syncthreads();
    return r;
}

// ---------------- per-row loss with histogram select ----------------------
__global__ __launch_bounds__(512)
void loss_kernel(int which, float* __restrict__ out, int oidx) {
    __shared__ float row[BDIM];
    __shared__ int   hist[NBINS];
    __shared__ int   ired[17];
    __shared__ float fred[17];
    __shared__ int   sbin[2];

    const float* dmat = which ? g_distT : g_dist;
    int r   = blockIdx.x;
    int tid = threadIdx.x;

    const float4* src = (const float4*)(dmat + (size_t)r * BDIM);
    float4* rowv = (float4*)row;
    for (int i = tid; i < BDIM / 4; i += 512) rowv[i] = src[i];
    __syncthreads();
    float pos = row[r];
    __syncthreads();
    if (tid == 0) row[r] = BIGV;  // exclude diagonal
    for (int i = tid; i < NBINS; i += 512) hist[i] = 0;
    __syncthreads();

    float thr   = MARGIN + pos;
    float inv_w = (float)NBINS / thr;

    int cnt = 0; float srelu = 0.f;
    for (int i = tid; i < BDIM; i += 512) {
        float d = row[i];
        if (d < thr) {
            cnt++; srelu += thr - d;
            int bin = (int)(d * inv_w);
            bin = bin > NBINS - 1 ? NBINS - 1 : (bin < 0 ? 0 : bin);
            atomicAdd(&hist[bin], 1);
        }
    }
    int Ctot = cnt; float Stot = srelu;
    block_reduce_if(Ctot, Stot, tid, ired, fred);

    if (Ctot <= KSEL) {
        if (tid == 0) atomicAdd(&out[oidx], Stot * SCALE);
        return;
    }

    int base = tid * (NBINS / 512);
    int lsum = 0;
#pragma unroll
    for (int j = 0; j < NBINS / 512; j++) lsum += hist[base + j];
    int pref = block_exscan512(lsum, tid, ired);
    if (pref < KSEL && KSEL <= pref + lsum) {
        int c = pref;
#pragma unroll
        for (int j = 0; j < NBINS / 512; j++) {
            int h = hist[base + j];
            if (c + h >= KSEL) { sbin[0] = base + j; sbin[1] = c; break; }
            c += h;
        }
    }
    __syncthreads();
    int   b1  = sbin[0];
    int   r1  = KSEL - sbin[1];
    float w1  = thr * (1.f / NBINS);
    float lo2 = b1 * w1;
    float inv_w2 = (float)NBINS / w1;

    for (int i = tid; i < NBINS; i += 512) hist[i] = 0;
    __syncthreads();
    for (int i = tid; i < BDIM; i += 512) {
        float d = row[i];
        if (d < thr) {
            int bin = (int)(d * inv_w);
            bin = bin > NBINS - 1 ? NBINS - 1 : (bin < 0 ? 0 : bin);
            if (bin == b1) {
                int sb = (int)((d - lo2) * inv_w2);
                sb = sb > NBINS - 1 ? NBINS - 1 : (sb < 0 ? 0 : sb);
                atomicAdd(&hist[sb], 1);
            }
        }
    }
    __syncthreads();
    int lsum2 = 0;
#pragma unroll
    for (int j = 0; j < NBINS / 512; j++) lsum2 += hist[base + j];
    int pref2 = block_exscan512(lsum2, tid, ired);
    if (pref2 < r1 && r1 <= pref2 + lsum2) {
        int c = pref2;
#pragma unroll
        for (int j = 0; j < NBINS / 512; j++) {
            int h = hist[base + j];
            if (c + h >= r1) { sbin[0] = base + j; break; }
            c += h;
        }
    }
    __syncthreads();
    float tstar = lo2 + sbin[0] * (w1 * (1.f / NBINS));

    int cl = 0; float sl = 0.f;
    for (int i = tid; i < BDIM; i += 512) {
        float d = row[i];
        if (d < tstar) { cl++; sl += d; }
    }
    block_reduce_if(cl, sl, tid, ired, fred);
    if (tid == 0) {
        float ssel = sl + (float)(KSEL - cl) * tstar;
        float loss = (float)KSEL * thr - ssel;
        atomicAdd(&out[oidx], loss * SCALE);
    }
}

// ---------------- launch ---------------------------------------------------
extern "C" void kernel_launch(void* const* d_in, const int* in_sizes, int n_in,
                              void* d_out, int out_size) {
    const float* x = (const float*)d_in[0];
    const float* y = (const float*)d_in[1];
    float* out = (float*)d_out;

    cudaFuncSetAttribute(gemm_dist_kernel,
                         cudaFuncAttributeMaxDynamicSharedMemorySize, GSMEM);

    zero_out_kernel<<<1, 32>>>(out);
    rowstats_kernel<<<dim3(BDIM, 2), 256>>>(x, y);
    gemm_dist_kernel<<<dim3(BDIM / GN, BDIM / GM), 128, GSMEM>>>(x, y);
    loss_kernel<<<BDIM, 512>>>(0, out, 0);
    loss_kernel<<<BDIM, 512>>>(1, out, 1);
}

// round 7
// speedup vs baseline: 1.6170x; 1.6170x over previous
#include <cuda_runtime.h>
#include <cuda.h>
#include <cstdint>

#define BDIM 4096
#define DDIM 1024
#define KSEL 1024
#define MARGIN 0.5f
#define EPSV 1e-6f
#define BIGV 1e6f
#define CEPS (1024.0f * 1e-6f * 1e-6f)   /* D * eps^2 */
#define SCALE (1.0f / (4096.0f * 1024.0f))
#define NBINS 4096

// GEMM tiling: block 128x128, BK=32, 128 threads (4 warps of 64x64)
#define GM 128
#define GN 128
#define BK 32
#define NKT (DDIM / BK)              /* 32 */
#define TILE_B 16384                 /* 128 rows x 128B (SW128 swizzled) */
#define OFF_B TILE_B
#define STAGE_B (2 * TILE_B)         /* 32768 */
#define SM_BUF0 1024
#define GSMEM 69632                  /* stages 66560B, epilogue 67584B */
#define STAGE_TX 32768u
#define CSTR 132                     /* epilogue transpose-stage stride (floats) */

// ---------------- device scratch (static: no allocations allowed) ----------
__device__ float g_dist[(size_t)BDIM * BDIM];
__device__ float g_distT[(size_t)BDIM * BDIM];
__device__ float g_a[BDIM];   // ||x||^2 + 2*eps*sum(x)
__device__ float g_b[BDIM];   // ||y||^2 - 2*eps*sum(y)

// ---------------- helpers --------------------------------------------------
__device__ __forceinline__ uint32_t smem_u32(const void* p) {
    return (uint32_t)__cvta_generic_to_shared(p);
}
__device__ __forceinline__ void mbar_init(uint32_t m, uint32_t cnt) {
    asm volatile("mbarrier.init.shared.b64 [%0], %1;" :: "r"(m), "r"(cnt) : "memory");
}
__device__ __forceinline__ void mbar_expect(uint32_t m, uint32_t bytes) {
    asm volatile("mbarrier.arrive.expect_tx.shared.b64 _, [%0], %1;"
                 :: "r"(m), "r"(bytes) : "memory");
}
__device__ __forceinline__ void mbar_wait(uint32_t m, uint32_t ph) {
    asm volatile(
        "{\n\t.reg .pred P;\n"
        "W%=:\n\t"
        "mbarrier.try_wait.parity.acquire.cta.shared::cta.b64 P, [%0], %1, 0x989680;\n\t"
        "@P bra D%=;\n\t"
        "bra W%=;\n"
        "D%=:\n\t}"
        :: "r"(m), "r"(ph) : "memory");
}
__device__ __forceinline__ void tma2d(uint32_t dst, const CUtensorMap* map,
                                      int cx, int cy, uint32_t mbar) {
    asm volatile(
        "cp.async.bulk.tensor.2d.shared::cluster.global.tile.mbarrier::complete_tx::bytes "
        "[%0], [%1, {%2, %3}], [%4];"
        :: "r"(dst), "l"(map), "r"(cx), "r"(cy), "r"(mbar) : "memory");
}
__device__ __forceinline__ void mma_tf32(float* c, uint32_t a0, uint32_t a1,
                                         uint32_t a2, uint32_t a3,
                                         uint32_t b0, uint32_t b1) {
    asm volatile(
        "mma.sync.aligned.m16n8k8.row.col.f32.tf32.tf32.f32 "
        "{%0,%1,%2,%3}, {%4,%5,%6,%7}, {%8,%9}, {%0,%1,%2,%3};"
        : "+f"(c[0]), "+f"(c[1]), "+f"(c[2]), "+f"(c[3])
        : "r"(a0), "r"(a1), "r"(a2), "r"(a3), "r"(b0), "r"(b1));
}

// ---------------- small kernels -------------------------------------------
__global__ void zero_out_kernel(float* out) {
    if (threadIdx.x == 0) { out[0] = 0.f; out[1] = 0.f; }
}

__global__ void rowstats_kernel(const float* __restrict__ X,
                                const float* __restrict__ Y) {
    __shared__ float r1s[8], r2s[8];
    int r = blockIdx.x;
    const float* p = (blockIdx.y == 0) ? X : Y;
    p += (size_t)r * DDIM;
    float s1 = 0.f, s2 = 0.f;
    for (int i = threadIdx.x; i < DDIM; i += 256) {
        float v = p[i]; s1 += v; s2 += v * v;
    }
    for (int o = 16; o; o >>= 1) {
        s1 += __shfl_down_sync(0xffffffffu, s1, o);
        s2 += __shfl_down_sync(0xffffffffu, s2, o);
    }
    int lane = threadIdx.x & 31, w = threadIdx.x >> 5;
    if (lane == 0) { r1s[w] = s1; r2s[w] = s2; }
    __syncthreads();
    if (threadIdx.x == 0) {
        s1 = 0.f; s2 = 0.f;
        for (int i = 0; i < 8; i++) { s1 += r1s[i]; s2 += r2s[i]; }
        if (blockIdx.y == 0) g_a[r] = s2 + 2.f * EPSV * s1;
        else                 g_b[r] = s2 - 2.f * EPSV * s1;
    }
}

// ---------------- tf32 mma.sync GEMM + fused transpose --------------------
// Stage loads: ONE cp.async.bulk.tensor.2d per tile (16KB, SW128 swizzle),
// completion via mbarrier expect_tx. Fragment LDS applies the SW128 XOR.
__global__ __launch_bounds__(128, 2)
void gemm_dist_kernel(const __grid_constant__ CUtensorMap tmx,
                      const __grid_constant__ CUtensorMap tmy) {
    extern __shared__ char smem[];
    const uint32_t sb = smem_u32(smem);
    const int tid  = threadIdx.x;
    const int lane = tid & 31, wid = tid >> 5;
    const int wm = wid & 1, wn = wid >> 1;   // 2x2 warp grid, 64x64 each
    const int g  = lane >> 2, tg = lane & 3;
    const int m0 = blockIdx.y * GM, n0 = blockIdx.x * GN;
    const uint32_t gx = (uint32_t)g * 16;    // SW128 row-phase XOR

    const uint32_t mb0 = sb, mb1 = sb + 16;
    if (tid == 0) { mbar_init(mb0, 1); mbar_init(mb1, 1); }
    __syncthreads();

    float acc[4][8][4];
#pragma unroll
    for (int mt = 0; mt < 4; mt++)
#pragma unroll
        for (int nt = 0; nt < 8; nt++)
#pragma unroll
            for (int q = 0; q < 4; q++) acc[mt][nt][q] = 0.f;

#define LOAD_STAGE(KT)                                                        \
    if (tid == 0) {                                                           \
        int _b = (KT) & 1;                                                    \
        uint32_t _mb = _b ? mb1 : mb0;                                        \
        uint32_t _buf = sb + SM_BUF0 + (uint32_t)_b * STAGE_B;                \
        mbar_expect(_mb, STAGE_TX);                                           \
        tma2d(_buf, &tmx, (KT) * BK, m0, _mb);                                \
        tma2d(_buf + OFF_B, &tmy, (KT) * BK, n0, _mb);                        \
    }

    LOAD_STAGE(0);
    LOAD_STAGE(1);

    for (int kt = 0; kt < NKT; kt++) {
        mbar_wait((kt & 1) ? mb1 : mb0, (kt >> 1) & 1);

        const char* abuf = smem + SM_BUF0 + (size_t)(kt & 1) * STAGE_B;
        const char* bbuf = abuf + OFF_B;

#pragma unroll
        for (int s = 0; s < 4; s++) {
            const uint32_t off = ((uint32_t)(s * 32 + tg * 8)) ^ gx;
            uint32_t A0[4], A1[4], A2[4], A3[4];
#pragma unroll
            for (int mt = 0; mt < 4; mt++) {
                int r = wm * 64 + mt * 16 + g;
                float2 lo = *(const float2*)(abuf + r * 128 + off);
                float2 hi = *(const float2*)(abuf + (r + 8) * 128 + off);
                A0[mt] = __float_as_uint(lo.x);
                A2[mt] = __float_as_uint(lo.y);
                A1[mt] = __float_as_uint(hi.x);
                A3[mt] = __float_as_uint(hi.y);
            }
#pragma unroll
            for (int nt = 0; nt < 8; nt++) {
                int n = wn * 64 + nt * 8 + g;
                float2 bv = *(const float2*)(bbuf + n * 128 + off);
                uint32_t B0 = __float_as_uint(bv.x);
                uint32_t B1 = __float_as_uint(bv.y);
                mma_tf32(acc[0][nt], A0[0], A1[0], A2[0], A3[0], B0, B1);
                mma_tf32(acc[1][nt], A0[1], A1[1], A2[1], A3[1], B0, B1);
                mma_tf32(acc[2][nt], A0[2], A1[2], A2[2], A3[2], B0, B1);
                mma_tf32(acc[3][nt], A0[3], A1[3], A2[3], A3[3], B0, B1);
            }
        }
        __syncthreads();                 // all warps done reading this buffer
        if (kt + 2 < NKT) LOAD_STAGE(kt + 2);
    }

    // epilogue: distances; direct write to g_dist, smem-staged for g_distT
    float* Csh = (float*)smem;
#pragma unroll
    for (int mt = 0; mt < 4; mt++) {
        int r0 = wm * 64 + mt * 16 + g;
        float a0 = g_a[m0 + r0] + CEPS;
        float a1 = g_a[m0 + r0 + 8] + CEPS;
#pragma unroll
        for (int nt = 0; nt < 8; nt++) {
            int c = wn * 64 + nt * 8 + 2 * tg;
            float b0 = g_b[n0 + c], b1 = g_b[n0 + c + 1];
            float* a4 = acc[mt][nt];
            float o00 = sqrtf(fmaxf(a0 + b0 - 2.f * a4[0], 0.f));
            float o01 = sqrtf(fmaxf(a0 + b1 - 2.f * a4[1], 0.f));
            float o10 = sqrtf(fmaxf(a1 + b0 - 2.f * a4[2], 0.f));
            float o11 = sqrtf(fmaxf(a1 + b1 - 2.f * a4[3], 0.f));
            *(float2*)&g_dist[(size_t)(m0 + r0) * BDIM + n0 + c] =
                make_float2(o00, o01);
            *(float2*)&g_dist[(size_t)(m0 + r0 + 8) * BDIM + n0 + c] =
                make_float2(o10, o11);
            Csh[c * CSTR + r0]           = o00;
            Csh[(c + 1) * CSTR + r0]     = o01;
            Csh[c * CSTR + r0 + 8]       = o10;
            Csh[(c + 1) * CSTR + r0 + 8] = o11;
        }
    }
    __syncthreads();
    // write transposed tile: 128 rows x 32 float4
#pragma unroll
    for (int i = tid; i < 128 * 32; i += 128) {
        int j = i >> 5, q = i & 31;
        float4 v = *(float4*)&Csh[j * CSTR + 4 * q];
        *(float4*)&g_distT[(size_t)(n0 + j) * BDIM + m0 + 4 * q] = v;
    }
}

// ---------------- block helpers (512 threads) -----------------------------
__device__ __forceinline__ void block_reduce_if(int& ci, float& sf, int tid,
                                                int* ired, float* fred) {
    for (int o = 16; o; o >>= 1) {
        ci += __shfl_down_sync(0xffffffffu, ci, o);
        sf += __shfl_down_sync(0xffffffffu, sf, o);
    }
    int lane = tid & 31, w = tid >> 5;
    if (lane == 0) { ired[w] = ci; fred[w] = sf; }
    __syncthreads();
    if (tid < 32) {
        int c = (tid < 16) ? ired[tid] : 0;
        float s = (tid < 16) ? fred[tid] : 0.f;
        for (int o = 8; o; o >>= 1) {
            c += __shfl_down_sync(0xffffffffu, c, o);
            s += __shfl_down_sync(0xffffffffu, s, o);
        }
        if (tid == 0) { ired[16] = c; fred[16] = s; }
    }
    __syncthreads();
    ci = ired[16]; sf = fred[16];
    __syncthreads();
}

__device__ __forceinline__ int block_exscan512(int v, int tid, int* sc) {
    int lane = tid & 31, w = tid >> 5;
    int x = v;
    for (int o = 1; o < 32; o <<= 1) {
        int t = __shfl_up_sync(0xffffffffu, x, o);
        if (lane >= o) x += t;
    }
    if (lane == 31) sc[w] = x;
    __syncthreads();
    if (tid < 32) {
        int ws = (tid < 16) ? sc[tid] : 0;
        for (int o = 1; o < 16; o <<= 1) {
            int t = __shfl_up_sync(0xffffffffu, ws, o);
            if (lane >= o) ws += t;
        }
        if (tid < 16) sc[tid] = ws;
    }
    __syncthreads();
    int off = (w > 0) ? sc[w - 1] : 0;
    int r = off + x - v;
    __syncthreads();
    return r;
}

// ---------------- per-row loss with histogram select ----------------------
__global__ __launch_bounds__(512)
void loss_kernel(int which, float* __restrict__ out, int oidx) {
    __shared__ float row[BDIM];
    __shared__ int   hist[NBINS];
    __shared__ int   ired[17];
    __shared__ float fred[17];
    __shared__ int   sbin[2];

    const float* dmat = which ? g_distT : g_dist;
    int r   = blockIdx.x;
    int tid = threadIdx.x;

    const float4* src = (const float4*)(dmat + (size_t)r * BDIM);
    float4* rowv = (float4*)row;
    for (int i = tid; i < BDIM / 4; i += 512) rowv[i] = src[i];
    __syncthreads();
    float pos = row[r];
    __syncthreads();
    if (tid == 0) row[r] = BIGV;  // exclude diagonal
    for (int i = tid; i < NBINS; i += 512) hist[i] = 0;
    __syncthreads();

    float thr   = MARGIN + pos;
    float inv_w = (float)NBINS / thr;

    int cnt = 0; float srelu = 0.f;
    for (int i = tid; i < BDIM; i += 512) {
        float d = row[i];
        if (d < thr) {
            cnt++; srelu += thr - d;
            int bin = (int)(d * inv_w);
            bin = bin > NBINS - 1 ? NBINS - 1 : (bin < 0 ? 0 : bin);
            atomicAdd(&hist[bin], 1);
        }
    }
    int Ctot = cnt; float Stot = srelu;
    block_reduce_if(Ctot, Stot, tid, ired, fred);

    if (Ctot <= KSEL) {
        if (tid == 0) atomicAdd(&out[oidx], Stot * SCALE);
        return;
    }

    int base = tid * (NBINS / 512);
    int lsum = 0;
#pragma unroll
    for (int j = 0; j < NBINS / 512; j++) lsum += hist[base + j];
    int pref = block_exscan512(lsum, tid, ired);
    if (pref < KSEL && KSEL <= pref + lsum) {
        int c = pref;
#pragma unroll
        for (int j = 0; j < NBINS / 512; j++) {
            int h = hist[base + j];
            if (c + h >= KSEL) { sbin[0] = base + j; sbin[1] = c; break; }
            c += h;
        }
    }
    __syncthreads();
    int   b1  = sbin[0];
    int   r1  = KSEL - sbin[1];
    float w1  = thr * (1.f / NBINS);
    float lo2 = b1 * w1;
    float inv_w2 = (float)NBINS / w1;

    for (int i = tid; i < NBINS; i += 512) hist[i] = 0;
    __syncthreads();
    for (int i = tid; i < BDIM; i += 512) {
        float d = row[i];
        if (d < thr) {
            int bin = (int)(d * inv_w);
            bin = bin > NBINS - 1 ? NBINS - 1 : (bin < 0 ? 0 : bin);
            if (bin == b1) {
                int sb = (int)((d - lo2) * inv_w2);
                sb = sb > NBINS - 1 ? NBINS - 1 : (sb < 0 ? 0 : sb);
                atomicAdd(&hist[sb], 1);
            }
        }
    }
    __syncthreads();
    int lsum2 = 0;
#pragma unroll
    for (int j = 0; j < NBINS / 512; j++) lsum2 += hist[base + j];
    int pref2 = block_exscan512(lsum2, tid, ired);
    if (pref2 < r1 && r1 <= pref2 + lsum2) {
        int c = pref2;
#pragma unroll
        for (int j = 0; j < NBINS / 512; j++) {
            int h = hist[base + j];
            if (c + h >= r1) { sbin[0] = base + j; break; }
            c += h;
        }
    }
    __syncthreads();
    float tstar = lo2 + sbin[0] * (w1 * (1.f / NBINS));

    int cl = 0; float sl = 0.f;
    for (int i = tid; i < BDIM; i += 512) {
        float d = row[i];
        if (d < tstar) { cl++; sl += d; }
    }
    block_reduce_if(cl, sl, tid, ired, fred);
    if (tid == 0) {
        float ssel = sl + (float)(KSEL - cl) * tstar;
        float loss = (float)KSEL * thr - ssel;
        atomicAdd(&out[oidx], loss * SCALE);
    }
}

// ---------------- host: tensormap building --------------------------------
typedef CUresult (*EncFn)(CUtensorMap*, CUtensorMapDataType, cuuint32_t, void*,
                          const cuuint64_t*, const cuuint64_t*, const cuuint32_t*,
                          const cuuint32_t*, CUtensorMapInterleave,
                          CUtensorMapSwizzle, CUtensorMapL2promotion,
                          CUtensorMapFloatOOBfill);

static void build_map(CUtensorMap* tm, const void* ptr) {
    static EncFn enc = nullptr;
    if (!enc) {
        cudaDriverEntryPointQueryResult qr;
#if CUDART_VERSION >= 12050
        cudaGetDriverEntryPointByVersion("cuTensorMapEncodeTiled", (void**)&enc,
                                         12000, cudaEnableDefault, &qr);
#else
        cudaGetDriverEntryPoint("cuTensorMapEncodeTiled", (void**)&enc,
                                cudaEnableDefault, &qr);
#endif
    }
    cuuint64_t dims[2] = {DDIM, BDIM};
    cuuint64_t strides[1] = {DDIM * sizeof(float)};
    cuuint32_t box[2] = {BK, GM};
    cuuint32_t es[2] = {1, 1};
    enc(tm, CU_TENSOR_MAP_DATA_TYPE_FLOAT32, 2, (void*)ptr, dims, strides, box,
        es, CU_TENSOR_MAP_INTERLEAVE_NONE, CU_TENSOR_MAP_SWIZZLE_128B,
        CU_TENSOR_MAP_L2_PROMOTION_L2_128B, CU_TENSOR_MAP_FLOAT_OOB_FILL_NONE);
}

// ---------------- launch ---------------------------------------------------
extern "C" void kernel_launch(void* const* d_in, const int* in_sizes, int n_in,
                              void* d_out, int out_size) {
    const float* x = (const float*)d_in[0];
    const float* y = (const float*)d_in[1];
    float* out = (float*)d_out;

    static CUtensorMap tmx, tmy;
    build_map(&tmx, x);
    build_map(&tmy, y);

    cudaFuncSetAttribute(gemm_dist_kernel,
                         cudaFuncAttributeMaxDynamicSharedMemorySize, GSMEM);

    zero_out_kernel<<<1, 32>>>(out);
    rowstats_kernel<<<dim3(BDIM, 2), 256>>>(x, y);
    gemm_dist_kernel<<<dim3(BDIM / GN, BDIM / GM), 128, GSMEM>>>(tmx, tmy);
    loss_kernel<<<BDIM, 512>>>(0, out, 0);
    loss_kernel<<<BDIM, 512>>>(1, out, 1);
}

// round 8
// speedup vs baseline: 2.3910x; 1.4787x over previous
#include <cuda_runtime.h>
#include <cuda.h>
#include <cuda_fp16.h>
#include <cstdint>

#define BDIM 4096
#define DDIM 1024
#define KSEL 1024
#define MARGIN 0.5f
#define EPSV 1e-6f
#define CEPS (1024.0f * 1e-6f * 1e-6f)   /* D * eps^2 */
#define SCALE (1.0f / (4096.0f * 1024.0f))
#define NBINS 4096

// GEMM tiling: block 128x128, BK=64 halves, 128 threads (4 warps of 64x64)
#define GM 128
#define GN 128
#define BK 64
#define NKT (DDIM / BK)              /* 16 */
#define TILE_B 16384                 /* 128 rows x 128B (fp16, SW128) */
#define OFF_B TILE_B
#define STAGE_B (2 * TILE_B)         /* 32768 */
#define SM_BUF0 1024
#define GSMEM 69632                  /* stages 66560B, epilogue 67584B */
#define STAGE_TX 32768u
#define CSTR 132                     /* epilogue transpose-stage stride (floats) */

// ---------------- device scratch (static: no allocations allowed) ----------
__device__ float g_dist[(size_t)BDIM * BDIM];
__device__ float g_distT[(size_t)BDIM * BDIM];
__device__ float g_a[BDIM];   // ||x||^2 + 2*eps*sum(x)
__device__ float g_b[BDIM];   // ||y||^2 - 2*eps*sum(y)
__device__ __half g_xh[(size_t)BDIM * DDIM];
__device__ __half g_yh[(size_t)BDIM * DDIM];

// ---------------- helpers --------------------------------------------------
__device__ __forceinline__ uint32_t smem_u32(const void* p) {
    return (uint32_t)__cvta_generic_to_shared(p);
}
__device__ __forceinline__ void mbar_init(uint32_t m, uint32_t cnt) {
    asm volatile("mbarrier.init.shared.b64 [%0], %1;" :: "r"(m), "r"(cnt) : "memory");
}
__device__ __forceinline__ void mbar_expect(uint32_t m, uint32_t bytes) {
    asm volatile("mbarrier.arrive.expect_tx.shared.b64 _, [%0], %1;"
                 :: "r"(m), "r"(bytes) : "memory");
}
__device__ __forceinline__ void mbar_wait(uint32_t m, uint32_t ph) {
    asm volatile(
        "{\n\t.reg .pred P;\n"
        "W%=:\n\t"
        "mbarrier.try_wait.parity.acquire.cta.shared::cta.b64 P, [%0], %1, 0x989680;\n\t"
        "@P bra D%=;\n\t"
        "bra W%=;\n"
        "D%=:\n\t}"
        :: "r"(m), "r"(ph) : "memory");
}
__device__ __forceinline__ void tma2d(uint32_t dst, const CUtensorMap* map,
                                      int cx, int cy, uint32_t mbar) {
    asm volatile(
        "cp.async.bulk.tensor.2d.shared::cluster.global.tile.mbarrier::complete_tx::bytes "
        "[%0], [%1, {%2, %3}], [%4];"
        :: "r"(dst), "l"(map), "r"(cx), "r"(cy), "r"(mbar) : "memory");
}
__device__ __forceinline__ void ldsm4(uint32_t& r0, uint32_t& r1, uint32_t& r2,
                                      uint32_t& r3, uint32_t addr) {
    asm volatile(
        "ldmatrix.sync.aligned.m8n8.x4.shared.b16 {%0,%1,%2,%3}, [%4];"
        : "=r"(r0), "=r"(r1), "=r"(r2), "=r"(r3) : "r"(addr));
}
__device__ __forceinline__ void mma_f16(float* c, uint32_t a0, uint32_t a1,
                                        uint32_t a2, uint32_t a3,
                                        uint32_t b0, uint32_t b1) {
    asm volatile(
        "mma.sync.aligned.m16n8k16.row.col.f32.f16.f16.f32 "
        "{%0,%1,%2,%3}, {%4,%5,%6,%7}, {%8,%9}, {%0,%1,%2,%3};"
        : "+f"(c[0]), "+f"(c[1]), "+f"(c[2]), "+f"(c[3])
        : "r"(a0), "r"(a1), "r"(a2), "r"(a3), "r"(b0), "r"(b1));
}

// ---------------- small kernels -------------------------------------------
__global__ void zero_out_kernel(float* out) {
    if (threadIdx.x == 0) { out[0] = 0.f; out[1] = 0.f; }
}

__global__ void rowstats_kernel(const float* __restrict__ X,
                                const float* __restrict__ Y) {
    __shared__ float r1s[8], r2s[8];
    int r = blockIdx.x;
    const float* p = (blockIdx.y == 0) ? X : Y;
    p += (size_t)r * DDIM;
    float s1 = 0.f, s2 = 0.f;
    for (int i = threadIdx.x; i < DDIM; i += 256) {
        float v = p[i]; s1 += v; s2 += v * v;
    }
    for (int o = 16; o; o >>= 1) {
        s1 += __shfl_down_sync(0xffffffffu, s1, o);
        s2 += __shfl_down_sync(0xffffffffu, s2, o);
    }
    int lane = threadIdx.x & 31, w = threadIdx.x >> 5;
    if (lane == 0) { r1s[w] = s1; r2s[w] = s2; }
    __syncthreads();
    if (threadIdx.x == 0) {
        s1 = 0.f; s2 = 0.f;
        for (int i = 0; i < 8; i++) { s1 += r1s[i]; s2 += r2s[i]; }
        if (blockIdx.y == 0) g_a[r] = s2 + 2.f * EPSV * s1;
        else                 g_b[r] = s2 - 2.f * EPSV * s1;
    }
}

// fp32 -> fp16 conversion (RN)
__global__ void convert_kernel(const float* __restrict__ X,
                               const float* __restrict__ Y) {
    size_t idx = (size_t)blockIdx.x * blockDim.x + threadIdx.x;  // float4 idx
    if (idx >= (size_t)BDIM * DDIM / 4) return;
    float4 vx = ((const float4*)X)[idx];
    float4 vy = ((const float4*)Y)[idx];
    __half hx[4] = {__float2half_rn(vx.x), __float2half_rn(vx.y),
                    __float2half_rn(vx.z), __float2half_rn(vx.w)};
    __half hy[4] = {__float2half_rn(vy.x), __float2half_rn(vy.y),
                    __float2half_rn(vy.z), __float2half_rn(vy.w)};
    ((uint2*)g_xh)[idx] = *(uint2*)hx;
    ((uint2*)g_yh)[idx] = *(uint2*)hy;
}

// ---------------- fp16 mma.sync GEMM + fused transpose --------------------
// TMA 2D fp16 tiles (SW128), ldmatrix.x4 fragments, m16n8k16 f16 MMA.
__global__ __launch_bounds__(128, 2)
void gemm_dist_kernel(const __grid_constant__ CUtensorMap tmx,
                      const __grid_constant__ CUtensorMap tmy) {
    extern __shared__ char smem[];
    const uint32_t sb = smem_u32(smem);
    const int tid  = threadIdx.x;
    const int lane = tid & 31, wid = tid >> 5;
    const int wm = wid & 1, wn = wid >> 1;   // 2x2 warp grid, 64x64 each
    const int g  = lane >> 2, tg = lane & 3;
    const int m0 = blockIdx.y * GM, n0 = blockIdx.x * GN;

    // per-lane ldmatrix addressing (SW128: row r XORs (r&7)*16 into col bytes)
    const int row_in = lane & 7;
    const uint32_t rowx = (uint32_t)row_in * 16;
    const int a_half = (lane >> 3) & 1;      // +8 rows for m1/m3
    const int a_kseg = lane >> 4;            // +16B for m2/m3
    const int quad   = lane >> 3;
    const int b_radd = (quad >> 1) * 8;      // +8 rows for m2/m3
    const int b_kseg = quad & 1;             // +16B for m1/m3
    uint32_t arow[4], brow[4];
#pragma unroll
    for (int mt = 0; mt < 4; mt++)
        arow[mt] = (uint32_t)(wm * 64 + mt * 16 + row_in + 8 * a_half) * 128;
#pragma unroll
    for (int p = 0; p < 4; p++)
        brow[p] = (uint32_t)(wn * 64 + p * 16 + row_in + b_radd) * 128;

    const uint32_t mb0 = sb, mb1 = sb + 16;
    if (tid == 0) { mbar_init(mb0, 1); mbar_init(mb1, 1); }
    __syncthreads();

    float acc[4][8][4];
#pragma unroll
    for (int mt = 0; mt < 4; mt++)
#pragma unroll
        for (int nt = 0; nt < 8; nt++)
#pragma unroll
            for (int q = 0; q < 4; q++) acc[mt][nt][q] = 0.f;

#define LOAD_STAGE(KT)                                                        \
    if (tid == 0) {                                                           \
        int _b = (KT) & 1;                                                    \
        uint32_t _mb = _b ? mb1 : mb0;                                        \
        uint32_t _buf = sb + SM_BUF0 + (uint32_t)_b * STAGE_B;                \
        mbar_expect(_mb, STAGE_TX);                                           \
        tma2d(_buf, &tmx, (KT) * BK, m0, _mb);                                \
        tma2d(_buf + OFF_B, &tmy, (KT) * BK, n0, _mb);                        \
    }

    LOAD_STAGE(0);
    LOAD_STAGE(1);

    for (int kt = 0; kt < NKT; kt++) {
        mbar_wait((kt & 1) ? mb1 : mb0, (kt >> 1) & 1);

        const uint32_t abuf = sb + SM_BUF0 + (uint32_t)(kt & 1) * STAGE_B;
        const uint32_t bbuf = abuf + OFF_B;

#pragma unroll
        for (int s = 0; s < 4; s++) {
            const uint32_t offa = ((uint32_t)(s * 32 + a_kseg * 16)) ^ rowx;
            const uint32_t offb = ((uint32_t)(s * 32 + b_kseg * 16)) ^ rowx;
            uint32_t A0[4], A1[4], A2[4], A3[4];
#pragma unroll
            for (int mt = 0; mt < 4; mt++)
                ldsm4(A0[mt], A1[mt], A2[mt], A3[mt], abuf + arow[mt] + offa);
            uint32_t B0[8], B1[8];
#pragma unroll
            for (int p = 0; p < 4; p++)
                ldsm4(B0[2 * p], B1[2 * p], B0[2 * p + 1], B1[2 * p + 1],
                      bbuf + brow[p] + offb);
#pragma unroll
            for (int nt = 0; nt < 8; nt++) {
                mma_f16(acc[0][nt], A0[0], A1[0], A2[0], A3[0], B0[nt], B1[nt]);
                mma_f16(acc[1][nt], A0[1], A1[1], A2[1], A3[1], B0[nt], B1[nt]);
                mma_f16(acc[2][nt], A0[2], A1[2], A2[2], A3[2], B0[nt], B1[nt]);
                mma_f16(acc[3][nt], A0[3], A1[3], A2[3], A3[3], B0[nt], B1[nt]);
            }
        }
        __syncthreads();                 // all warps done reading this buffer
        if (kt + 2 < NKT) LOAD_STAGE(kt + 2);
    }

    // epilogue: distances; direct write to g_dist, smem-staged for g_distT
    float* Csh = (float*)smem;
#pragma unroll
    for (int mt = 0; mt < 4; mt++) {
        int r0 = wm * 64 + mt * 16 + g;
        float a0 = g_a[m0 + r0] + CEPS;
        float a1 = g_a[m0 + r0 + 8] + CEPS;
#pragma unroll
        for (int nt = 0; nt < 8; nt++) {
            int c = wn * 64 + nt * 8 + 2 * tg;
            float b0 = g_b[n0 + c], b1 = g_b[n0 + c + 1];
            float* a4 = acc[mt][nt];
            float o00 = sqrtf(fmaxf(a0 + b0 - 2.f * a4[0], 0.f));
            float o01 = sqrtf(fmaxf(a0 + b1 - 2.f * a4[1], 0.f));
            float o10 = sqrtf(fmaxf(a1 + b0 - 2.f * a4[2], 0.f));
            float o11 = sqrtf(fmaxf(a1 + b1 - 2.f * a4[3], 0.f));
            *(float2*)&g_dist[(size_t)(m0 + r0) * BDIM + n0 + c] =
                make_float2(o00, o01);
            *(float2*)&g_dist[(size_t)(m0 + r0 + 8) * BDIM + n0 + c] =
                make_float2(o10, o11);
            Csh[c * CSTR + r0]           = o00;
            Csh[(c + 1) * CSTR + r0]     = o01;
            Csh[c * CSTR + r0 + 8]       = o10;
            Csh[(c + 1) * CSTR + r0 + 8] = o11;
        }
    }
    __syncthreads();
#pragma unroll
    for (int i = tid; i < 128 * 32; i += 128) {
        int j = i >> 5, q = i & 31;
        float4 v = *(float4*)&Csh[j * CSTR + 4 * q];
        *(float4*)&g_distT[(size_t)(n0 + j) * BDIM + m0 + 4 * q] = v;
    }
}

// ---------------- loss: single pass + count/sum histograms ----------------
__device__ __forceinline__ void block_reduce_if(int& ci, float& sf, int tid,
                                                int* ired, float* fred) {
    for (int o = 16; o; o >>= 1) {
        ci += __shfl_down_sync(0xffffffffu, ci, o);
        sf += __shfl_down_sync(0xffffffffu, sf, o);
    }
    int lane = tid & 31, w = tid >> 5;
    if (lane == 0) { ired[w] = ci; fred[w] = sf; }
    __syncthreads();
    if (tid < 32) {
        int c = (tid < 16) ? ired[tid] : 0;
        float s = (tid < 16) ? fred[tid] : 0.f;
        for (int o = 8; o; o >>= 1) {
            c += __shfl_down_sync(0xffffffffu, c, o);
            s += __shfl_down_sync(0xffffffffu, s, o);
        }
        if (tid == 0) { ired[16] = c; fred[16] = s; }
    }
    __syncthreads();
    ci = ired[16]; sf = fred[16];
    __syncthreads();
}

// exclusive scan of (int, float) pairs across 512 threads
__device__ __forceinline__ void exscan_cf(int v, float f, int tid, int* sci,
                                          float* scf, int& oc, float& of) {
    int lane = tid & 31, w = tid >> 5;
    int xc = v; float xf = f;
    for (int o = 1; o < 32; o <<= 1) {
        int tc = __shfl_up_sync(0xffffffffu, xc, o);
        float tf = __shfl_up_sync(0xffffffffu, xf, o);
        if (lane >= o) { xc += tc; xf += tf; }
    }
    if (lane == 31) { sci[w] = xc; scf[w] = xf; }
    __syncthreads();
    if (tid < 32) {
        int wc = (tid < 16) ? sci[tid] : 0;
        float wf = (tid < 16) ? scf[tid] : 0.f;
        for (int o = 1; o < 16; o <<= 1) {
            int tc = __shfl_up_sync(0xffffffffu, wc, o);
            float tf = __shfl_up_sync(0xffffffffu, wf, o);
            if (lane >= o) { wc += tc; wf += tf; }
        }
        if (tid < 16) { sci[tid] = wc; scf[tid] = wf; }
    }
    __syncthreads();
    int offc = (w > 0) ? sci[w - 1] : 0;
    float offf = (w > 0) ? scf[w - 1] : 0.f;
    oc = offc + xc - v;
    of = offf + xf - f;
    __syncthreads();
}

__global__ __launch_bounds__(512)
void loss_kernel(float* __restrict__ out) {
    __shared__ int   histc[NBINS];
    __shared__ float hists[NBINS];
    __shared__ int   ired[17];
    __shared__ float fred[17];
    __shared__ float spos;
    __shared__ int   sb1;
    __shared__ int   sCb;
    __shared__ float sSb;

    const int which = blockIdx.y;
    const float* dmat = which ? g_distT : g_dist;
    const int r   = blockIdx.x;
    const int tid = threadIdx.x;

    for (int i = tid; i < NBINS; i += 512) { histc[i] = 0; hists[i] = 0.f; }
    if (tid == 0) spos = dmat[(size_t)r * BDIM + r];
    __syncthreads();

    const float thr   = spos + MARGIN;
    const float inv_w = (float)NBINS / thr;

    const float4* src = (const float4*)(dmat + (size_t)r * BDIM);
    int cnt = 0; float srelu = 0.f;
#pragma unroll
    for (int it = 0; it < 2; it++) {
        int i4 = tid + it * 512;
        float4 v = src[i4];
        int base = i4 * 4;
        float dv[4] = {v.x, v.y, v.z, v.w};
#pragma unroll
        for (int e = 0; e < 4; e++) {
            float d = dv[e];
            if (base + e != r && d < thr) {
                cnt++; srelu += thr - d;
                int bin = (int)(d * inv_w);
                bin = bin > NBINS - 1 ? NBINS - 1 : bin;
                atomicAdd(&histc[bin], 1);
                atomicAdd(&hists[bin], d);
            }
        }
    }
    int Ctot = cnt; float Stot = srelu;
    block_reduce_if(Ctot, Stot, tid, ired, fred);

    if (Ctot <= KSEL) {
        if (tid == 0) atomicAdd(&out[which], Stot * SCALE);
        return;
    }

    // locate rank-K bin; sum counts & values strictly below it
    int base = tid * (NBINS / 512);
    int lc = 0; float ls = 0.f;
#pragma unroll
    for (int j = 0; j < NBINS / 512; j++) { lc += histc[base + j]; ls += hists[base + j]; }
    int pc; float ps;
    exscan_cf(lc, ls, tid, ired, fred, pc, ps);
    if (pc < KSEL && KSEL <= pc + lc) {
        int c = pc; float s = ps;
#pragma unroll
        for (int j = 0; j < NBINS / 512; j++) {
            int h = histc[base + j];
            if (c + h >= KSEL) { sb1 = base + j; sCb = c; sSb = s; break; }
            c += h; s += hists[base + j];
        }
    }
    __syncthreads();
    if (tid == 0) {
        float tstar = (float)sb1 * (thr / (float)NBINS);
        float ssel = sSb + (float)(KSEL - sCb) * tstar;
        float loss = (float)KSEL * thr - ssel;
        atomicAdd(&out[which], loss * SCALE);
    }
}

// ---------------- host: tensormap building --------------------------------
typedef CUresult (*EncFn)(CUtensorMap*, CUtensorMapDataType, cuuint32_t, void*,
                          const cuuint64_t*, const cuuint64_t*, const cuuint32_t*,
                          const cuuint32_t*, CUtensorMapInterleave,
                          CUtensorMapSwizzle, CUtensorMapL2promotion,
                          CUtensorMapFloatOOBfill);

static void build_map_h(CUtensorMap* tm, void* ptr) {
    static EncFn enc = nullptr;
    if (!enc) {
        cudaDriverEntryPointQueryResult qr;
#if CUDART_VERSION >= 12050
        cudaGetDriverEntryPointByVersion("cuTensorMapEncodeTiled", (void**)&enc,
                                         12000, cudaEnableDefault, &qr);
#else
        cudaGetDriverEntryPoint("cuTensorMapEncodeTiled", (void**)&enc,
                                cudaEnableDefault, &qr);
#endif
    }
    cuuint64_t dims[2] = {DDIM, BDIM};
    cuuint64_t strides[1] = {DDIM * sizeof(__half)};
    cuuint32_t box[2] = {BK, GM};
    cuuint32_t es[2] = {1, 1};
    enc(tm, CU_TENSOR_MAP_DATA_TYPE_UINT16, 2, ptr, dims, strides, box,
        es, CU_TENSOR_MAP_INTERLEAVE_NONE, CU_TENSOR_MAP_SWIZZLE_128B,
        CU_TENSOR_MAP_L2_PROMOTION_L2_128B, CU_TENSOR_MAP_FLOAT_OOB_FILL_NONE);
}

// ---------------- launch ---------------------------------------------------
extern "C" void kernel_launch(void* const* d_in, const int* in_sizes, int n_in,
                              void* d_out, int out_size) {
    const float* x = (const float*)d_in[0];
    const float* y = (const float*)d_in[1];
    float* out = (float*)d_out;

    static CUtensorMap tmx, tmy;
    void *pxh = nullptr, *pyh = nullptr;
    cudaGetSymbolAddress(&pxh, g_xh);
    cudaGetSymbolAddress(&pyh, g_yh);
    build_map_h(&tmx, pxh);
    build_map_h(&tmy, pyh);

    cudaFuncSetAttribute(gemm_dist_kernel,
                         cudaFuncAttributeMaxDynamicSharedMemorySize, GSMEM);

    zero_out_kernel<<<1, 32>>>(out);
    rowstats_kernel<<<dim3(BDIM, 2), 256>>>(x, y);
    convert_kernel<<<(BDIM * DDIM / 4 + 255) / 256, 256>>>(x, y);
    gemm_dist_kernel<<<dim3(BDIM / GN, BDIM / GM), 128, GSMEM>>>(tmx, tmy);
    loss_kernel<<<dim3(BDIM, 2), 512>>>(out);
}